// round 8
// baseline (speedup 1.0000x reference)
#include <cuda_runtime.h>
#include <stdint.h>

#define H 2048
#define W 2048
#define HW (H*W)

#define POS_CAP  (1<<22)
#define BIN_CAP  (1<<18)
#define CAND_CAP 16384

__device__ unsigned long long g_poslist[POS_CAP];
__device__ unsigned long long g_binlist[BIN_CAP];
__device__ unsigned long long g_cand[CAND_CAP];
__device__ unsigned int g_hist1[65536];
__device__ unsigned int g_hist2[65536];
__device__ int g_poscount;
__device__ int g_bincount;
__device__ int g_candcount;
__device__ unsigned int g_T1;
__device__ int g_Kprime;
__device__ unsigned int g_done1;
__device__ unsigned int g_done2;

// ---------------------------------------------------------------------------
// block-cooperative threshold select over a 65536-bin histogram (256 thr)
// ---------------------------------------------------------------------------
__device__ void select_thresh(const unsigned int* __restrict__ hist, int target,
                              unsigned int* scr, unsigned int* outT,
                              int* outKprime, int K) {
    unsigned int* csum = scr;          // 4096 chunk sums (16 bins each)
    unsigned int* suf  = scr + 4096;   // 256
    int t = threadIdx.x;

    unsigned int tot = 0u;
    #pragma unroll 4
    for (int c = 0; c < 16; c++) {
        int chunk = t * 16 + c;
        const uint4* p = (const uint4*)(hist + chunk * 16);
        unsigned int s = 0u;
        #pragma unroll
        for (int q = 0; q < 4; q++) { uint4 v = __ldg(&p[q]); s += v.x + v.y + v.z + v.w; }
        csum[chunk] = s;
        tot += s;
    }
    suf[t] = tot;
    __syncthreads();
    for (int off = 1; off < 256; off <<= 1) {
        unsigned int v = (t + off < 256) ? suf[t + off] : 0u;
        __syncthreads();
        suf[t] += v;
        __syncthreads();
    }
    unsigned int my  = suf[t];
    unsigned int nxt = (t < 255) ? suf[t + 1] : 0u;
    if (target > 0 && my >= (unsigned int)target && nxt < (unsigned int)target) {
        unsigned int run = nxt;
        for (int c = 15; c >= 0; c--) {
            int chunk = t * 16 + c;
            unsigned int cs = csum[chunk];
            if (run + cs >= (unsigned int)target) {
                unsigned int bins[16];
                const uint4* p = (const uint4*)(hist + chunk * 16);
                #pragma unroll
                for (int q = 0; q < 4; q++) {
                    uint4 v = __ldg(&p[q]);
                    bins[q*4] = v.x; bins[q*4+1] = v.y; bins[q*4+2] = v.z; bins[q*4+3] = v.w;
                }
                for (int b = 15; b >= 0; b--) {
                    unsigned int prev = run;
                    run += bins[b];
                    if (run >= (unsigned int)target) {
                        *outT = (unsigned int)(chunk * 16 + b);
                        if (outKprime) *outKprime = K - (int)prev;
                        break;
                    }
                }
                break;
            }
            run += cs;
        }
    }
}

// ---------------------------------------------------------------------------
__global__ void k_init(float* __restrict__ out_head, int K) {
    int i = blockIdx.x * blockDim.x + threadIdx.x;
    if (i < 65536) { g_hist1[i] = 0u; g_hist2[i] = 0u; }
    if (i == 0) {
        g_poscount = 0; g_bincount = 0; g_candcount = 0;
        g_T1 = 0u; g_Kprime = K; g_done1 = 0u; g_done2 = 0u;
    }
    if (i < 7 * K) out_head[i] = 0.0f;
}

// ---------------------------------------------------------------------------
// fused NMS3d (128x16 tile, 256 threads) + last-block T1 select
// ---------------------------------------------------------------------------
__global__ __launch_bounds__(256, 6)
void k_nms(const float* __restrict__ low, const float* __restrict__ cur,
           const float* __restrict__ high, const float* __restrict__ oct,
           float* __restrict__ oct_out, int K) {
    __shared__ float s_mem[18*136 + 16*128 + 18*128];
    __shared__ unsigned long long sbuf[1024];
    __shared__ unsigned int s_cnt;
    __shared__ int s_base;
    __shared__ bool s_last;

    float* sm  = s_mem;
    float* smc = s_mem + 18*136;
    float* hm  = smc + 16*128;

    int tid = threadIdx.x;
    if (tid == 0) s_cnt = 0u;

    int bx = blockIdx.x * 128, by = blockIdx.y * 16;

    for (int s = tid; s < 612; s += 256) {
        int r = s / 34, c = s - r * 34;
        int gy = by + r - 1;
        int gx = bx + c * 4 - 4;
        float4 m4 = make_float4(-1e30f, -1e30f, -1e30f, -1e30f);
        float4 c4 = m4;
        if ((unsigned)gy < (unsigned)H && (unsigned)gx < (unsigned)W) {
            int g = gy * W + gx;
            float4 l4 = __ldg((const float4*)(low + g));
            c4        = __ldg((const float4*)(cur + g));
            float4 h4 = __ldg((const float4*)(high + g));
            m4.x = fmaxf(fmaxf(l4.x, c4.x), h4.x);
            m4.y = fmaxf(fmaxf(l4.y, c4.y), h4.y);
            m4.z = fmaxf(fmaxf(l4.z, c4.z), h4.z);
            m4.w = fmaxf(fmaxf(l4.w, c4.w), h4.w);
        }
        *(float4*)&sm[r * 136 + c * 4] = m4;
        if (r >= 1 && r <= 16 && c >= 1 && c <= 32)
            *(float4*)&smc[(r - 1) * 128 + (c - 1) * 4] = c4;
    }
    __syncthreads();

    for (int e = tid; e < 2304; e += 256) {
        int r = e >> 7, cc = e & 127;
        const float* row = &sm[r * 136 + cc + 3];
        hm[r * 128 + cc] = fmaxf(fmaxf(row[0], row[1]), row[2]);
    }
    __syncthreads();

    int txl = tid & 31, tyw = tid >> 5;
    int px = txl * 4;
    #pragma unroll
    for (int grp = 0; grp < 2; grp++) {
        int yl = tyw + grp * 8;
        int y = by + yl;
        int x0 = bx + px;

        float4 m0 = *(float4*)&hm[yl * 128 + px];
        float4 m1 = *(float4*)&hm[(yl + 1) * 128 + px];
        float4 m2 = *(float4*)&hm[(yl + 2) * 128 + px];
        float mp[4] = { fmaxf(fmaxf(m0.x, m1.x), m2.x),
                        fmaxf(fmaxf(m0.y, m1.y), m2.y),
                        fmaxf(fmaxf(m0.z, m1.z), m2.z),
                        fmaxf(fmaxf(m0.w, m1.w), m2.w) };
        float4 cv4 = *(float4*)&smc[yl * 128 + px];
        float cv[4] = { cv4.x, cv4.y, cv4.z, cv4.w };
        float4 oc4 = __ldg((const float4*)(oct + y * W + x0));
        float oc[4] = { oc4.x, oc4.y, oc4.z, oc4.w };

        float nm[4], oo[4];
        bool ybord = (y == 0) || (y == H - 1);
        #pragma unroll
        for (int j = 0; j < 4; j++) {
            float v = ((cv[j] - mp[j]) + 1e-5f > 0.0f) ? cv[j] : 0.0f;
            int xx = x0 + j;
            if (ybord || xx == 0 || xx == W - 1) v = 0.0f;
            v *= (1.0f - oc[j]);
            nm[j] = v;
            oo[j] = (float)(unsigned char)(oc[j] + v);
        }
        *(float4*)(oct_out + y * W + x0) = make_float4(oo[0], oo[1], oo[2], oo[3]);

        #pragma unroll
        for (int j = 0; j < 4; j++) {
            if (nm[j] > 0.0f) {
                unsigned int bits = __float_as_uint(nm[j]);
                unsigned int p = atomicAdd(&s_cnt, 1u);
                if (p < 1024u)
                    sbuf[p] = ((unsigned long long)bits << 32) |
                              (unsigned int)(~(y * W + x0 + j));
            }
        }
    }
    __syncthreads();
    unsigned int cnt = min(s_cnt, 1024u);
    if (tid == 0 && cnt) s_base = atomicAdd(&g_poscount, (int)cnt);
    __syncthreads();

    unsigned int cntPad = (cnt + 255u) & ~255u;
    for (unsigned int i = tid; i < cntPad; i += 256) {
        bool valid = (i < cnt);
        unsigned long long key = valid ? sbuf[i] : 0ull;
        unsigned int bin = valid ? (unsigned int)(key >> 48)
                                 : (0x10000u + (unsigned int)(tid & 31));
        unsigned int mm = __match_any_sync(0xFFFFFFFFu, bin);
        if (valid) {
            int leader = __ffs(mm) - 1;
            if ((tid & 31) == leader)
                atomicAdd(&g_hist1[bin], (unsigned int)__popc(mm));
            int pos = s_base + (int)i;
            if (pos < POS_CAP) g_poslist[pos] = key;
        }
    }

    __threadfence();
    if (tid == 0) {
        unsigned int d = atomicAdd(&g_done1, 1u);
        s_last = (d == gridDim.x * gridDim.y - 1u);
    }
    __syncthreads();
    if (!s_last) return;
    select_thresh(g_hist1, K, (unsigned int*)s_mem, &g_T1, &g_Kprime, K);
}

// ---------------------------------------------------------------------------
// partition positives + last-block T2 select + binlist filter
// ---------------------------------------------------------------------------
__global__ __launch_bounds__(256)
void k_part() {
    __shared__ unsigned int wCand[8], wBin[8];
    __shared__ int candBase, binBase;
    __shared__ unsigned int scratch[4096 + 256];
    __shared__ unsigned int s_T2, s_off;
    __shared__ int s_base2;
    __shared__ bool s_last;

    int n = min(g_poscount, POS_CAP);
    unsigned int T1 = g_T1;
    int tid = threadIdx.x, lane = tid & 31, wid = tid >> 5;
    unsigned int laneLT = (1u << lane) - 1u;
    int total = gridDim.x * 256;
    int nIter = (n + total - 1) / total;

    for (int it = 0; it < nIter; it++) {
        int i = blockIdx.x * 256 + tid + it * total;
        bool valid = (i < n);
        unsigned long long key = valid ? g_poslist[i] : 0ull;
        unsigned int bin = (unsigned int)(key >> 48);
        bool toCand = valid && (bin > T1);
        bool toBin  = valid && (bin == T1);

        unsigned int mc = __ballot_sync(0xFFFFFFFFu, toCand);
        unsigned int mb = __ballot_sync(0xFFFFFFFFu, toBin);
        if (lane == 0) { wCand[wid] = (unsigned int)__popc(mc); wBin[wid] = (unsigned int)__popc(mb); }
        __syncthreads();
        if (tid == 0) {
            unsigned int tc = 0, tb = 0, pc[8], pb[8];
            #pragma unroll
            for (int w = 0; w < 8; w++) { pc[w] = tc; tc += wCand[w]; pb[w] = tb; tb += wBin[w]; }
            candBase = tc ? atomicAdd(&g_candcount, (int)tc) : 0;
            binBase  = tb ? atomicAdd(&g_bincount,  (int)tb) : 0;
            #pragma unroll
            for (int w = 0; w < 8; w++) { wCand[w] = pc[w]; wBin[w] = pb[w]; }
        }
        __syncthreads();
        if (toCand) {
            int pos = candBase + (int)wCand[wid] + __popc(mc & laneLT);
            if (pos < CAND_CAP) g_cand[pos] = key;
        }
        if (toBin) {
            unsigned int lo = (unsigned int)(key >> 32) & 0xFFFFu;
            unsigned int mm = __match_any_sync(mb, lo);
            if (lane == __ffs(mm) - 1)
                atomicAdd(&g_hist2[lo], (unsigned int)__popc(mm));
            int pos = binBase + (int)wBin[wid] + __popc(mb & laneLT);
            if (pos < BIN_CAP) g_binlist[pos] = key;
        }
        __syncthreads();
    }

    __threadfence();
    if (tid == 0) {
        unsigned int d = atomicAdd(&g_done2, 1u);
        s_last = (d == gridDim.x - 1u);
        s_T2 = 0u; s_off = 0u;
    }
    __syncthreads();
    if (!s_last) return;

    select_thresh(g_hist2, g_Kprime, scratch, &s_T2, 0, 0);
    __syncthreads();
    unsigned int T2 = s_T2;
    int n2 = min(g_bincount, BIN_CAP);
    if (tid == 0) s_base2 = g_candcount;
    __syncthreads();

    int n2pad = (n2 + 255) & ~255;
    for (int i = tid; i < n2pad; i += 256) {
        bool valid = (i < n2);
        unsigned long long key = valid ? g_binlist[i] : 0ull;
        bool pass = valid && (((unsigned int)(key >> 32) & 0xFFFFu) >= T2);
        unsigned int m = __ballot_sync(0xFFFFFFFFu, pass);
        if (pass) {
            int leader = __ffs(m) - 1;
            unsigned int wb;
            if (lane == leader) wb = atomicAdd(&s_off, (unsigned int)__popc(m));
            wb = __shfl_sync(m, wb, leader);
            int pos = s_base2 + (int)wb + __popc(m & laneLT);
            if (pos < CAND_CAP) g_cand[pos] = key;
        }
    }
    __syncthreads();
    if (tid == 0) {
        int tot2 = s_base2 + (int)s_off;
        g_candcount = tot2 < CAND_CAP ? tot2 : CAND_CAP;
    }
}

// ---------------------------------------------------------------------------
// exact rank: 32 candidates/block x 8 sub-threads, smem-tiled all-pairs,
// then per-rank centroid fit + LAF epilogue
// ---------------------------------------------------------------------------
#define RANK_CHUNK 4096

__global__ __launch_bounds__(256)
void k_rank(const float* __restrict__ low, const float* __restrict__ cur,
            const float* __restrict__ high, const float* __restrict__ aff,
            float* __restrict__ vals, float* __restrict__ lafs, int K) {
    int n = min(g_candcount, CAND_CAP);
    if ((int)blockIdx.x * 32 >= n) return;   // early exit before any smem work

    __shared__ unsigned long long sk[RANK_CHUNK];

    int tid = threadIdx.x;
    int ci = blockIdx.x * 32 + (tid >> 3);   // 32 candidates per block
    int sub = tid & 7;                       // 8 sub-threads per candidate
    bool active = (ci < n);
    unsigned long long my = active ? g_cand[ci] : 0xFFFFFFFFFFFFFFFFull;

    int cnt = 0;
    for (int base = 0; base < n; base += RANK_CHUNK) {
        int m = min(RANK_CHUNK, n - base);
        __syncthreads();
        for (int i = tid; i < m; i += 256)
            sk[i] = g_cand[base + i];
        __syncthreads();
        #pragma unroll 8
        for (int j = sub; j < m; j += 8)
            cnt += (sk[j] > my) ? 1 : 0;
    }

    cnt += __shfl_down_sync(0xFFFFFFFFu, cnt, 4, 8);
    cnt += __shfl_down_sync(0xFFFFFFFFu, cnt, 2, 8);
    cnt += __shfl_down_sync(0xFFFFFFFFu, cnt, 1, 8);

    if (sub != 0 || !active) return;
    int rank = cnt;
    if (rank >= K) return;

    unsigned int bits = (unsigned int)(my >> 32);
    int idx = (int)(~(unsigned int)(my & 0xFFFFFFFFull));
    int y = idx >> 11;
    int x = idx & 2047;

    float mass = 0.f, nz = 0.f, ny = 0.f, nx = 0.f;
    const float* planes[3] = { low, cur, high };
    #pragma unroll
    for (int dz = 0; dz < 3; dz++) {
        const float* p = planes[dz];
        float wz = (float)dz - 0.5f;
        #pragma unroll
        for (int dy = -1; dy <= 1; dy++) {
            float wy = (float)dy + 0.5f;
            #pragma unroll
            for (int dx = -1; dx <= 1; dx++) {
                float wx = (float)dx + 0.5f;
                float v = __ldg(&p[(y + dy) * W + (x + dx)]);
                mass += v;
                nz += wz * v; ny += wy * v; nx += wx * v;
            }
        }
    }
    float inv = 1.0f / (mass + 1e-8f);
    float sN = (nz * inv) * (1.0f / 2048.0f);
    float yN = (ny * inv + (float)y) * (1.0f / 2048.0f);
    float xN = (nx * inv + (float)x) * (1.0f / 2048.0f);

    float A00 = __ldg(&aff[idx]);
    float A01 = __ldg(&aff[HW + idx]);
    float A10 = __ldg(&aff[2 * HW + idx]);
    float A11 = __ldg(&aff[3 * HW + idx]);

    vals[rank] = __uint_as_float(bits);
    float* lf = lafs + rank * 6;
    lf[0] = sN * A00;
    lf[1] = sN * A01;
    lf[2] = xN;
    lf[3] = sN * A10;
    lf[4] = sN * A11;
    lf[5] = yN;
}

// ---------------------------------------------------------------------------
extern "C" void kernel_launch(void* const* d_in, const int* in_sizes, int n_in,
                              void* d_out, int out_size) {
    const float* low  = (const float*)d_in[0];
    const float* cur  = (const float*)d_in[1];
    const float* high = (const float*)d_in[2];
    const float* aff  = (const float*)d_in[3];
    const float* oct  = (const float*)d_in[4];

    int K = 4096;
    if (out_size > HW && ((out_size - HW) % 7) == 0) K = (out_size - HW) / 7;

    float* out    = (float*)d_out;
    float* vals   = out;
    float* lafs   = out + K;
    float* octout = out + 7 * K;

    int initN = 65536;
    if (7 * K > initN) initN = 7 * K;
    k_init<<<(initN + 255) / 256, 256>>>(out, K);

    dim3 g(W / 128, H / 16);
    k_nms<<<g, 256>>>(low, cur, high, oct, octout, K);

    k_part<<<1024, 256>>>();
    k_rank<<<CAND_CAP / 32, 256>>>(low, cur, high, aff, vals, lafs, K);
}

// round 11
// speedup vs baseline: 1.4303x; 1.4303x over previous
#include <cuda_runtime.h>
#include <stdint.h>

#define H 2048
#define W 2048
#define HW (H*W)

#define POS_CAP  (1<<22)
#define BIN_CAP  (1<<18)
#define CAND_CAP 16384

__device__ unsigned long long g_poslist[POS_CAP];
__device__ unsigned long long g_binlist[BIN_CAP];
__device__ unsigned long long g_cand[CAND_CAP];
__device__ unsigned int g_hist1[65536];
__device__ unsigned int g_hist2[65536];
__device__ int g_poscount;
__device__ int g_bincount;
__device__ int g_candcount;
__device__ int g_n1;
__device__ unsigned int g_T1;
__device__ int g_Kprime;
__device__ unsigned int g_done1;
__device__ unsigned int g_done2;

// ---------------------------------------------------------------------------
// block-cooperative threshold select over a 65536-bin histogram (256 thr)
// ---------------------------------------------------------------------------
__device__ void select_thresh(const unsigned int* __restrict__ hist, int target,
                              unsigned int* scr, unsigned int* outT,
                              int* outKprime, int K) {
    unsigned int* csum = scr;          // 4096 chunk sums (16 bins each)
    unsigned int* suf  = scr + 4096;   // 256
    int t = threadIdx.x;

    unsigned int tot = 0u;
    #pragma unroll 4
    for (int c = 0; c < 16; c++) {
        int chunk = t * 16 + c;
        const uint4* p = (const uint4*)(hist + chunk * 16);
        unsigned int s = 0u;
        #pragma unroll
        for (int q = 0; q < 4; q++) { uint4 v = __ldg(&p[q]); s += v.x + v.y + v.z + v.w; }
        csum[chunk] = s;
        tot += s;
    }
    suf[t] = tot;
    __syncthreads();
    for (int off = 1; off < 256; off <<= 1) {
        unsigned int v = (t + off < 256) ? suf[t + off] : 0u;
        __syncthreads();
        suf[t] += v;
        __syncthreads();
    }
    unsigned int my  = suf[t];
    unsigned int nxt = (t < 255) ? suf[t + 1] : 0u;
    if (target > 0 && my >= (unsigned int)target && nxt < (unsigned int)target) {
        unsigned int run = nxt;
        for (int c = 15; c >= 0; c--) {
            int chunk = t * 16 + c;
            unsigned int cs = csum[chunk];
            if (run + cs >= (unsigned int)target) {
                unsigned int bins[16];
                const uint4* p = (const uint4*)(hist + chunk * 16);
                #pragma unroll
                for (int q = 0; q < 4; q++) {
                    uint4 v = __ldg(&p[q]);
                    bins[q*4] = v.x; bins[q*4+1] = v.y; bins[q*4+2] = v.z; bins[q*4+3] = v.w;
                }
                for (int b = 15; b >= 0; b--) {
                    unsigned int prev = run;
                    run += bins[b];
                    if (run >= (unsigned int)target) {
                        *outT = (unsigned int)(chunk * 16 + b);
                        if (outKprime) *outKprime = K - (int)prev;
                        break;
                    }
                }
                break;
            }
            run += cs;
        }
    }
}

// ---------------------------------------------------------------------------
__global__ void k_init(float* __restrict__ out_head, int K) {
    int i = blockIdx.x * blockDim.x + threadIdx.x;
    if (i < 65536) { g_hist1[i] = 0u; g_hist2[i] = 0u; }
    if (i == 0) {
        g_poscount = 0; g_bincount = 0; g_candcount = 0; g_n1 = 0;
        g_T1 = 0u; g_Kprime = K; g_done1 = 0u; g_done2 = 0u;
    }
    if (i < 7 * K) out_head[i] = 0.0f;
}

// ---------------------------------------------------------------------------
// fused NMS3d (128x16 tile, 256 threads) + last-block T1 select
// ---------------------------------------------------------------------------
__global__ __launch_bounds__(256, 6)
void k_nms(const float* __restrict__ low, const float* __restrict__ cur,
           const float* __restrict__ high, const float* __restrict__ oct,
           float* __restrict__ oct_out, int K) {
    __shared__ float s_mem[18*136 + 16*128 + 18*128];
    __shared__ unsigned long long sbuf[1024];
    __shared__ unsigned int s_cnt;
    __shared__ int s_base;
    __shared__ bool s_last;

    float* sm  = s_mem;
    float* smc = s_mem + 18*136;
    float* hm  = smc + 16*128;

    int tid = threadIdx.x;
    if (tid == 0) s_cnt = 0u;

    int bx = blockIdx.x * 128, by = blockIdx.y * 16;

    for (int s = tid; s < 612; s += 256) {
        int r = s / 34, c = s - r * 34;
        int gy = by + r - 1;
        int gx = bx + c * 4 - 4;
        float4 m4 = make_float4(-1e30f, -1e30f, -1e30f, -1e30f);
        float4 c4 = m4;
        if ((unsigned)gy < (unsigned)H && (unsigned)gx < (unsigned)W) {
            int g = gy * W + gx;
            float4 l4 = __ldg((const float4*)(low + g));
            c4        = __ldg((const float4*)(cur + g));
            float4 h4 = __ldg((const float4*)(high + g));
            m4.x = fmaxf(fmaxf(l4.x, c4.x), h4.x);
            m4.y = fmaxf(fmaxf(l4.y, c4.y), h4.y);
            m4.z = fmaxf(fmaxf(l4.z, c4.z), h4.z);
            m4.w = fmaxf(fmaxf(l4.w, c4.w), h4.w);
        }
        *(float4*)&sm[r * 136 + c * 4] = m4;
        if (r >= 1 && r <= 16 && c >= 1 && c <= 32)
            *(float4*)&smc[(r - 1) * 128 + (c - 1) * 4] = c4;
    }
    __syncthreads();

    for (int e = tid; e < 2304; e += 256) {
        int r = e >> 7, cc = e & 127;
        const float* row = &sm[r * 136 + cc + 3];
        hm[r * 128 + cc] = fmaxf(fmaxf(row[0], row[1]), row[2]);
    }
    __syncthreads();

    int txl = tid & 31, tyw = tid >> 5;
    int px = txl * 4;
    #pragma unroll
    for (int grp = 0; grp < 2; grp++) {
        int yl = tyw + grp * 8;
        int y = by + yl;
        int x0 = bx + px;

        float4 m0 = *(float4*)&hm[yl * 128 + px];
        float4 m1 = *(float4*)&hm[(yl + 1) * 128 + px];
        float4 m2 = *(float4*)&hm[(yl + 2) * 128 + px];
        float mp[4] = { fmaxf(fmaxf(m0.x, m1.x), m2.x),
                        fmaxf(fmaxf(m0.y, m1.y), m2.y),
                        fmaxf(fmaxf(m0.z, m1.z), m2.z),
                        fmaxf(fmaxf(m0.w, m1.w), m2.w) };
        float4 cv4 = *(float4*)&smc[yl * 128 + px];
        float cv[4] = { cv4.x, cv4.y, cv4.z, cv4.w };
        float4 oc4 = __ldg((const float4*)(oct + y * W + x0));
        float oc[4] = { oc4.x, oc4.y, oc4.z, oc4.w };

        float nm[4], oo[4];
        bool ybord = (y == 0) || (y == H - 1);
        #pragma unroll
        for (int j = 0; j < 4; j++) {
            float v = ((cv[j] - mp[j]) + 1e-5f > 0.0f) ? cv[j] : 0.0f;
            int xx = x0 + j;
            if (ybord || xx == 0 || xx == W - 1) v = 0.0f;
            v *= (1.0f - oc[j]);
            nm[j] = v;
            oo[j] = (float)(unsigned char)(oc[j] + v);
        }
        *(float4*)(oct_out + y * W + x0) = make_float4(oo[0], oo[1], oo[2], oo[3]);

        #pragma unroll
        for (int j = 0; j < 4; j++) {
            if (nm[j] > 0.0f) {
                unsigned int bits = __float_as_uint(nm[j]);
                unsigned int p = atomicAdd(&s_cnt, 1u);
                if (p < 1024u)
                    sbuf[p] = ((unsigned long long)bits << 32) |
                              (unsigned int)(~(y * W + x0 + j));
            }
        }
    }
    __syncthreads();
    unsigned int cnt = min(s_cnt, 1024u);
    if (tid == 0 && cnt) s_base = atomicAdd(&g_poscount, (int)cnt);
    __syncthreads();

    unsigned int cntPad = (cnt + 255u) & ~255u;
    for (unsigned int i = tid; i < cntPad; i += 256) {
        bool valid = (i < cnt);
        unsigned long long key = valid ? sbuf[i] : 0ull;
        unsigned int bin = valid ? (unsigned int)(key >> 48)
                                 : (0x10000u + (unsigned int)(tid & 31));
        unsigned int mm = __match_any_sync(0xFFFFFFFFu, bin);
        if (valid) {
            int leader = __ffs(mm) - 1;
            if ((tid & 31) == leader)
                atomicAdd(&g_hist1[bin], (unsigned int)__popc(mm));
            int pos = s_base + (int)i;
            if (pos < POS_CAP) g_poslist[pos] = key;
        }
    }

    __threadfence();
    if (tid == 0) {
        unsigned int d = atomicAdd(&g_done1, 1u);
        s_last = (d == gridDim.x * gridDim.y - 1u);
    }
    __syncthreads();
    if (!s_last) return;
    select_thresh(g_hist1, K, (unsigned int*)s_mem, &g_T1, &g_Kprime, K);
}

// ---------------------------------------------------------------------------
// partition positives + last-block T2 select + binlist filter
// ---------------------------------------------------------------------------
__global__ __launch_bounds__(256)
void k_part() {
    __shared__ unsigned int wCand[8], wBin[8];
    __shared__ int candBase, binBase;
    __shared__ unsigned int scratch[4096 + 256];
    __shared__ unsigned int s_T2, s_off;
    __shared__ int s_base2;
    __shared__ bool s_last;

    int n = min(g_poscount, POS_CAP);
    unsigned int T1 = g_T1;
    int tid = threadIdx.x, lane = tid & 31, wid = tid >> 5;
    unsigned int laneLT = (1u << lane) - 1u;
    int total = gridDim.x * 256;
    int nIter = (n + total - 1) / total;

    for (int it = 0; it < nIter; it++) {
        int i = blockIdx.x * 256 + tid + it * total;
        bool valid = (i < n);
        unsigned long long key = valid ? g_poslist[i] : 0ull;
        unsigned int bin = (unsigned int)(key >> 48);
        bool toCand = valid && (bin > T1);
        bool toBin  = valid && (bin == T1);

        unsigned int mc = __ballot_sync(0xFFFFFFFFu, toCand);
        unsigned int mb = __ballot_sync(0xFFFFFFFFu, toBin);
        if (lane == 0) { wCand[wid] = (unsigned int)__popc(mc); wBin[wid] = (unsigned int)__popc(mb); }
        __syncthreads();
        if (tid == 0) {
            unsigned int tc = 0, tb = 0, pc[8], pb[8];
            #pragma unroll
            for (int w = 0; w < 8; w++) { pc[w] = tc; tc += wCand[w]; pb[w] = tb; tb += wBin[w]; }
            candBase = tc ? atomicAdd(&g_candcount, (int)tc) : 0;
            binBase  = tb ? atomicAdd(&g_bincount,  (int)tb) : 0;
            #pragma unroll
            for (int w = 0; w < 8; w++) { wCand[w] = pc[w]; wBin[w] = pb[w]; }
        }
        __syncthreads();
        if (toCand) {
            int pos = candBase + (int)wCand[wid] + __popc(mc & laneLT);
            if (pos < CAND_CAP) g_cand[pos] = key;
        }
        if (toBin) {
            unsigned int lo = (unsigned int)(key >> 32) & 0xFFFFu;
            unsigned int mm = __match_any_sync(mb, lo);
            if (lane == __ffs(mm) - 1)
                atomicAdd(&g_hist2[lo], (unsigned int)__popc(mm));
            int pos = binBase + (int)wBin[wid] + __popc(mb & laneLT);
            if (pos < BIN_CAP) g_binlist[pos] = key;
        }
        __syncthreads();
    }

    __threadfence();
    if (tid == 0) {
        unsigned int d = atomicAdd(&g_done2, 1u);
        s_last = (d == gridDim.x - 1u);
        s_T2 = 0u; s_off = 0u;
    }
    __syncthreads();
    if (!s_last) return;

    select_thresh(g_hist2, g_Kprime, scratch, &s_T2, 0, 0);
    __syncthreads();
    unsigned int T2 = s_T2;
    int n2 = min(g_bincount, BIN_CAP);
    if (tid == 0) { s_base2 = g_candcount; g_n1 = g_candcount; }
    __syncthreads();

    int n2pad = (n2 + 255) & ~255;
    for (int i = tid; i < n2pad; i += 256) {
        bool valid = (i < n2);
        unsigned long long key = valid ? g_binlist[i] : 0ull;
        bool pass = valid && (((unsigned int)(key >> 32) & 0xFFFFu) >= T2);
        unsigned int m = __ballot_sync(0xFFFFFFFFu, pass);
        if (pass) {
            int leader = __ffs(m) - 1;
            unsigned int wb;
            if (lane == leader) wb = atomicAdd(&s_off, (unsigned int)__popc(m));
            wb = __shfl_sync(m, wb, leader);
            int pos = s_base2 + (int)wb + __popc(m & laneLT);
            if (pos < CAND_CAP) g_cand[pos] = key;
        }
    }
    __syncthreads();
    if (tid == 0) {
        int tot2 = s_base2 + (int)s_off;
        g_candcount = tot2 < CAND_CAP ? tot2 : CAND_CAP;
    }
}

// ---------------------------------------------------------------------------
// exact rank: one candidate per WARP, group-split compare range, coalesced
// L1-hot LDG scan, warp-parallel centroid/LAF epilogue
// ---------------------------------------------------------------------------
__global__ __launch_bounds__(256)
void k_rank(const float* __restrict__ low, const float* __restrict__ cur,
            const float* __restrict__ high, const float* __restrict__ aff,
            float* __restrict__ vals, float* __restrict__ lafs, int K) {
    int n = min(g_candcount, CAND_CAP);
    if ((int)blockIdx.x * 8 >= n) return;          // 8 candidates (warps) / block

    int n1 = min(g_n1, n);
    int lane = threadIdx.x & 31;
    int ci = blockIdx.x * 8 + (threadIdx.x >> 5);
    if (ci >= n) return;                           // whole-warp exit

    unsigned long long my = __ldg(&g_cand[ci]);

    // group split: group1 keys (bin > T1) all outrank group2 (bin == T1)
    int lo, hi, base;
    if (ci < n1) { lo = 0;  hi = n1; base = 0;  }
    else         { lo = n1; hi = n;  base = n1; }

    unsigned int cnt = 0;
    int j = lo + lane;
    // unrolled-by-4 scan for MLP
    for (; j + 96 < hi; j += 128) {
        unsigned long long k0 = __ldg(&g_cand[j]);
        unsigned long long k1 = __ldg(&g_cand[j + 32]);
        unsigned long long k2 = __ldg(&g_cand[j + 64]);
        unsigned long long k3 = __ldg(&g_cand[j + 96]);
        cnt += (k0 > my) + (k1 > my) + (k2 > my) + (k3 > my);
    }
    for (; j < hi; j += 32)
        cnt += (__ldg(&g_cand[j]) > my) ? 1u : 0u;

    cnt = __reduce_add_sync(0xFFFFFFFFu, cnt);
    int rank = base + (int)cnt;
    if (rank >= K) return;

    unsigned int bits = (unsigned int)(my >> 32);
    int idx = (int)(~(unsigned int)(my & 0xFFFFFFFFull));
    int y = idx >> 11;
    int x = idx & 2047;

    // warp-parallel 3x3x3 centroid fit: lanes 0..26 take one tap each
    float mass = 0.f, nz = 0.f, ny = 0.f, nx = 0.f;
    if (lane < 27) {
        int dz = lane / 9;
        int rem = lane - dz * 9;
        int dy = rem / 3 - 1;
        int dx = rem - (dy + 1) * 3 - 1;
        const float* p = (dz == 0) ? low : (dz == 1) ? cur : high;
        float v = __ldg(&p[(y + dy) * W + (x + dx)]);
        mass = v;
        nz = ((float)dz - 0.5f) * v;
        ny = ((float)dy + 0.5f) * v;
        nx = ((float)dx + 0.5f) * v;
    }
    float a = 0.f;
    if (lane >= 27 && lane < 31)
        a = __ldg(&aff[(lane - 27) * HW + idx]);

    #pragma unroll
    for (int off = 16; off > 0; off >>= 1) {
        mass += __shfl_down_sync(0xFFFFFFFFu, mass, off);
        nz   += __shfl_down_sync(0xFFFFFFFFu, nz, off);
        ny   += __shfl_down_sync(0xFFFFFFFFu, ny, off);
        nx   += __shfl_down_sync(0xFFFFFFFFu, nx, off);
    }
    float A00 = __shfl_sync(0xFFFFFFFFu, a, 27);
    float A01 = __shfl_sync(0xFFFFFFFFu, a, 28);
    float A10 = __shfl_sync(0xFFFFFFFFu, a, 29);
    float A11 = __shfl_sync(0xFFFFFFFFu, a, 30);

    if (lane != 0) return;
    float inv = 1.0f / (mass + 1e-8f);
    float sN = (nz * inv) * (1.0f / 2048.0f);
    float yN = (ny * inv + (float)y) * (1.0f / 2048.0f);
    float xN = (nx * inv + (float)x) * (1.0f / 2048.0f);

    vals[rank] = __uint_as_float(bits);
    float* lf = lafs + rank * 6;
    lf[0] = sN * A00;
    lf[1] = sN * A01;
    lf[2] = xN;
    lf[3] = sN * A10;
    lf[4] = sN * A11;
    lf[5] = yN;
}

// ---------------------------------------------------------------------------
extern "C" void kernel_launch(void* const* d_in, const int* in_sizes, int n_in,
                              void* d_out, int out_size) {
    const float* low  = (const float*)d_in[0];
    const float* cur  = (const float*)d_in[1];
    const float* high = (const float*)d_in[2];
    const float* aff  = (const float*)d_in[3];
    const float* oct  = (const float*)d_in[4];

    int K = 4096;
    if (out_size > HW && ((out_size - HW) % 7) == 0) K = (out_size - HW) / 7;

    float* out    = (float*)d_out;
    float* vals   = out;
    float* lafs   = out + K;
    float* octout = out + 7 * K;

    int initN = 65536;
    if (7 * K > initN) initN = 7 * K;
    k_init<<<(initN + 255) / 256, 256>>>(out, K);

    dim3 g(W / 128, H / 16);
    k_nms<<<g, 256>>>(low, cur, high, oct, octout, K);

    k_part<<<1024, 256>>>();
    k_rank<<<CAND_CAP / 8, 256>>>(low, cur, high, aff, vals, lafs, K);
}